// round 4
// baseline (speedup 1.0000x reference)
#include <cuda_runtime.h>
#include <math.h>

#define PP   33
#define IMG  256
#define NT   1024

__device__ __forceinline__ float2 cmul(float2 a, float2 b) {
    return make_float2(fmaf(a.x, b.x, -a.y * b.y), fmaf(a.x, b.y, a.y * b.x));
}

__global__ __launch_bounds__(NT, 1)
void taper_kernel(const float* __restrict__ ref,
                  const float* __restrict__ mov,
                  const int* __restrict__ xp,
                  const int* __restrict__ yp,
                  float* __restrict__ out, int B) {
    __shared__ float  patch[PP][PP + 3];   // 16B-aligned rows
    __shared__ float2 Ts[PP][PP + 1];      // Ts[i][a]
    __shared__ float2 Tt[PP][PP + 1];      // Tt[b][j] = Ts[j][b]
    __shared__ float2 V[PP][PP + 1];       // V[i][b]
    __shared__ float2 Abase[PP];           // e^{-2pi i (n_q+1)/479}
    __shared__ float2 Ccol[PP];            // e^{-2pi i as/479}
    __shared__ float  Wrow[PP][2];         // w0, w1 per row

    int b = blockIdx.x;
    const float* img;
    float2* o;
    if (b < B) {
        img = ref + (size_t)b * IMG * IMG;
        o   = (float2*)out + (size_t)b * PP * PP;
    } else {
        img = mov + (size_t)(b - B) * IMG * IMG;
        o   = (float2*)out + (size_t)B * PP * PP + (size_t)(b - B) * PP * PP;
    }
    int x0 = xp ? __ldg(xp) : 100;
    int y0 = yp ? __ldg(yp) : 50;

    int tid = threadIdx.x;

    // Phase A0: 66 threads compute the only transcendentals in the kernel;
    // everyone stages the patch (LDG latency overlaps the MUFU work).
    if (tid < PP) {
        int q = tid;
        int ii = q + 16; if (ii >= PP) ii -= PP;
        int n16 = 478 * ii;
        int n = n16 >> 5;
        float f = (float)(n16 & 31) * 0.03125f;
        float s, c;
        sincospif((float)(-2 * (n + 1)) * (1.0f / 479.0f), &s, &c);
        Abase[q] = make_float2(c, s);
        Wrow[q][0] = 479.0f * (1.0f - f);
        Wrow[q][1] = 479.0f * f;
    } else if (tid < 2 * PP) {
        int r = tid - PP;
        float s, c;
        sincospif((float)(-2 * (r - 16)) * (1.0f / 479.0f), &s, &c);
        Ccol[r] = make_float2(c, s);
    }
    for (int idx = tid; idx < PP * PP; idx += NT) {
        int q = idx / PP, r = idx - q * PP;
        patch[q][r] = img[(size_t)(x0 + q) * IMG + (y0 + r)];
    }
    __syncthreads();

    // Phase A1: T[q][r] = (w0 + w1*C[r]) * A[q]^{as} via square-and-multiply.
    for (int idx = tid; idx < PP * PP; idx += NT) {
        int q = idx / PP, r = idx - q * PP;
        int as = r - 16;
        unsigned u = (unsigned)abs(as);
        float2 base = Abase[q];
        float2 res = make_float2(1.0f, 0.0f);
#pragma unroll
        for (int k = 0; k < 5; k++) {
            float2 rm = cmul(res, base);
            if ((u >> k) & 1u) res = rm;
            base = cmul(base, base);
        }
        if (as < 0) res.y = -res.y;
        float2 C = Ccol[r];
        float w0 = Wrow[q][0], w1 = Wrow[q][1];
        float2 pre = make_float2(fmaf(w1, C.x, w0), w1 * C.y);
        float2 t = cmul(pre, res);
        Ts[q][r] = t;
        Tt[r][q] = t;
    }
    __syncthreads();

    // Stage 1: V[i][b] = sum_a Ts[i][a] * patch[a][b]   (complex x real)
    for (int idx = tid; idx < PP * PP; idx += NT) {
        int i = idx / PP, bb = idx - i * PP;
        const float4* trow = reinterpret_cast<const float4*>(Ts[i]);
        float rx = 0.f, ry = 0.f, rx2 = 0.f, ry2 = 0.f;
#pragma unroll
        for (int h = 0; h < 16; h++) {
            float4 tv = trow[h];
            float p0 = patch[2 * h][bb];
            float p1 = patch[2 * h + 1][bb];
            rx  = fmaf(tv.x, p0, rx);
            ry  = fmaf(tv.y, p0, ry);
            rx2 = fmaf(tv.z, p1, rx2);
            ry2 = fmaf(tv.w, p1, ry2);
        }
        float2 tl = Ts[i][32];
        float  pl = patch[32][bb];
        V[i][bb] = make_float2(fmaf(tl.x, pl, rx + rx2),
                               fmaf(tl.y, pl, ry + ry2));
    }
    __syncthreads();

    // Stage 2: out[i][j] = sum_b V[i][b] * Tt[b][j]   (complex x complex)
    for (int idx = tid; idx < PP * PP; idx += NT) {
        int i = idx / PP, j = idx - i * PP;
        const float4* vrow = reinterpret_cast<const float4*>(V[i]);
        float rxx = 0.f, ryy = 0.f, rxy = 0.f, ryx = 0.f;
#pragma unroll
        for (int h = 0; h < 16; h++) {
            float4 vv = vrow[h];
            float2 t0 = Tt[2 * h][j];
            float2 t1 = Tt[2 * h + 1][j];
            rxx = fmaf(vv.x, t0.x, rxx);
            ryy = fmaf(vv.y, t0.y, ryy);
            rxy = fmaf(vv.x, t0.y, rxy);
            ryx = fmaf(vv.y, t0.x, ryx);
            rxx = fmaf(vv.z, t1.x, rxx);
            ryy = fmaf(vv.w, t1.y, ryy);
            rxy = fmaf(vv.z, t1.y, rxy);
            ryx = fmaf(vv.w, t1.x, ryx);
        }
        float2 vl = V[i][32];
        float2 tl = Tt[32][j];
        rxx = fmaf(vl.x, tl.x, rxx);
        ryy = fmaf(vl.y, tl.y, ryy);
        rxy = fmaf(vl.x, tl.y, rxy);
        ryx = fmaf(vl.y, tl.x, ryx);
        o[idx] = make_float2(rxx - ryy, rxy + ryx);
    }
}

extern "C" void kernel_launch(void* const* d_in, const int* in_sizes, int n_in,
                              void* d_out, int out_size) {
    const float* ref = (const float*)d_in[0];
    const float* mov = (const float*)d_in[1];
    const int* xp = (n_in > 2) ? (const int*)d_in[2] : nullptr;
    const int* yp = (n_in > 3) ? (const int*)d_in[3] : nullptr;
    float* out = (float*)d_out;
    int B = in_sizes[0] / (IMG * IMG);

    taper_kernel<<<2 * B, NT>>>(ref, mov, xp, yp, out, B);
}

// round 6
// speedup vs baseline: 1.0226x; 1.0226x over previous
#include <cuda_runtime.h>
#include <math.h>

#define PP   33
#define IMG  256
#define NT   1024   // 32 warps; warp w handles rows w and w+32 (only w=0 gets 2)

__global__ __launch_bounds__(NT, 1)
void taper_kernel(const float* __restrict__ ref,
                  const float* __restrict__ mov,
                  const int* __restrict__ xp,
                  const int* __restrict__ yp,
                  float* __restrict__ out, int B) {
    __shared__ float  patch[PP][PP + 3];   // 144B rows, 16B aligned
    __shared__ float2 Ts[PP][PP + 1];      // Ts[i][a] (uniform row reads, stage 1)
    __shared__ float2 Tt[PP][PP + 1];      // Tt[b][j] = Ts[j][b] (lane reads, stage 2)

    int b = blockIdx.x;
    const float* img;
    float2* o;
    if (b < B) {
        img = ref + (size_t)b * IMG * IMG;
        o   = (float2*)out + (size_t)b * PP * PP;
    } else {
        img = mov + (size_t)(b - B) * IMG * IMG;
        o   = (float2*)out + (size_t)B * PP * PP + (size_t)(b - B) * PP * PP;
    }
    int x0 = xp ? __ldg(xp) : 100;
    int y0 = yp ? __ldg(yp) : 50;

    int tid  = threadIdx.x;
    int w    = tid >> 5;        // warp id
    int lane = tid & 31;        // lane = output column (0..31); col 32 uniform

    // ---- Phase A: build T (per-element sincospif overlaps LDG) + stage patch
    for (int idx = tid; idx < PP * PP; idx += NT) {
        int q = idx / PP, r = idx - q * PP;

        int ii  = q + 16; if (ii >= PP) ii -= PP;   // undo ifftshift
        int n16 = 478 * ii;                          // c_reg = ii*478/32 exact
        int n   = n16 >> 5;
        float f = (float)(n16 & 31) * 0.03125f;
        int as  = r - 16;
        float s1, c1, s2, c2;
        sincospif((float)(-2 * as * (n + 1)) * (1.0f / 479.0f), &s1, &c1);
        sincospif((float)(-2 * as * (n + 2)) * (1.0f / 479.0f), &s2, &c2);
        float w0 = 479.0f * (1.0f - f), w1 = 479.0f * f;
        float2 t = make_float2(fmaf(w0, c1, w1 * c2), fmaf(w0, s1, w1 * s2));
        Ts[q][r] = t;
        Tt[r][q] = t;

        patch[q][r] = img[(size_t)(x0 + q) * IMG + (y0 + r)];
    }
    __syncthreads();

    // Each warp owns output row(s): row = w, then w+32 (only warp 0 loops twice).
    for (int row = w; row < PP; row += 32) {
        // ---- Stage 1: V[row][j] = sum_a Ts[row][a] * patch[a][j] (complex x real)
        float vx = 0.f, vy = 0.f;          // V[row][lane]
        float v32x = 0.f, v32y = 0.f;      // V[row][32]
#pragma unroll
        for (int a = 0; a < PP; a++) {
            float2 t  = Ts[row][a];        // warp-uniform broadcast
            float  p   = patch[a][lane];   // stride-1
            float  p32 = patch[a][32];     // uniform
            vx   = fmaf(t.x, p,   vx);
            vy   = fmaf(t.y, p,   vy);
            v32x = fmaf(t.x, p32, v32x);
            v32y = fmaf(t.y, p32, v32y);
        }
        // No block sync needed: stage 2 of this row consumes only this warp's V.

        // ---- Stage 2: out[row][j] = sum_b V[row][b] * Tt[b][j] (complex x complex)
        float rxx = 0.f, ryy = 0.f, rxy = 0.f, ryx = 0.f;   // j = lane
        float sxx = 0.f, syy = 0.f, sxy = 0.f, syx = 0.f;   // j = 32
#pragma unroll
        for (int bb = 0; bb < PP; bb++) {
            float ux, uy;
            if (bb < 32) {
                ux = __shfl_sync(0xffffffffu, vx, bb);
                uy = __shfl_sync(0xffffffffu, vy, bb);
            } else {
                ux = v32x; uy = v32y;
            }
            float2 t   = Tt[bb][lane];     // stride-1
            float2 t32 = Tt[bb][32];       // uniform
            rxx = fmaf(ux, t.x, rxx);
            ryy = fmaf(uy, t.y, ryy);
            rxy = fmaf(ux, t.y, rxy);
            ryx = fmaf(uy, t.x, ryx);
            sxx = fmaf(ux, t32.x, sxx);
            syy = fmaf(uy, t32.y, syy);
            sxy = fmaf(ux, t32.y, sxy);
            syx = fmaf(uy, t32.x, syx);
        }

        float2* orow = o + (size_t)row * PP;
        orow[lane] = make_float2(rxx - ryy, rxy + ryx);
        if (lane == 0)
            orow[32] = make_float2(sxx - syy, sxy + syx);
    }
}

extern "C" void kernel_launch(void* const* d_in, const int* in_sizes, int n_in,
                              void* d_out, int out_size) {
    const float* ref = (const float*)d_in[0];
    const float* mov = (const float*)d_in[1];
    const int* xp = (n_in > 2) ? (const int*)d_in[2] : nullptr;
    const int* yp = (n_in > 3) ? (const int*)d_in[3] : nullptr;
    float* out = (float*)d_out;
    int B = in_sizes[0] / (IMG * IMG);

    taper_kernel<<<2 * B, NT>>>(ref, mov, xp, yp, out, B);
}

// round 7
// speedup vs baseline: 1.2179x; 1.1910x over previous
#include <cuda_runtime.h>
#include <math.h>

#define PP   33
#define IMG  256
#define NT   1024
#define ROWS0 17                 // block half 0: rows 0..16 ; half 1: rows 17..32

__global__ __launch_bounds__(NT, 2)
void taper_kernel(const float* __restrict__ ref,
                  const float* __restrict__ mov,
                  const int* __restrict__ xp,
                  const int* __restrict__ yp,
                  float* __restrict__ out, int B) {
    __shared__ float  patch[PP][PP + 3];    // 16B-aligned rows
    __shared__ float2 Ts[PP][PP + 1];       // Ts[i][a]
    __shared__ float2 Tt[PP][PP + 1];       // Tt[b][j] = Ts[j][b]
    __shared__ float2 V[ROWS0][PP + 1];     // this block's V rows

    int blk  = blockIdx.x;
    int ib   = blk >> 1;                    // image index (0..2B-1)
    int half = blk & 1;                     // 0: rows 0..16, 1: rows 17..32
    int rowbase = half ? ROWS0 : 0;
    int nrows   = half ? (PP - ROWS0) : ROWS0;

    const float* img;
    float2* o;
    if (ib < B) {
        img = ref + (size_t)ib * IMG * IMG;
        o   = (float2*)out + (size_t)ib * PP * PP;
    } else {
        img = mov + (size_t)(ib - B) * IMG * IMG;
        o   = (float2*)out + (size_t)B * PP * PP + (size_t)(ib - B) * PP * PP;
    }
    int x0 = xp ? __ldg(xp) : 100;
    int y0 = yp ? __ldg(yp) : 50;

    int tid = threadIdx.x;

    // ---- Phase A: full T build + patch stage (1089 items, 65 threads loop twice;
    //      LDG issued first so its latency overlaps the sincospif chain)
    for (int idx = tid; idx < PP * PP; idx += NT) {
        int q = idx / PP, r = idx - q * PP;

        float pv = img[(size_t)(x0 + q) * IMG + (y0 + r)];   // issue LDG early

        int ii  = q + 16; if (ii >= PP) ii -= PP;   // undo ifftshift
        int n16 = 478 * ii;                          // c = ii*478/32 exactly
        int n   = n16 >> 5;
        float f = (float)(n16 & 31) * 0.03125f;
        int as  = r - 16;
        float s1, c1, s2, c2;
        sincospif((float)(-2 * as * (n + 1)) * (1.0f / 479.0f), &s1, &c1);
        sincospif((float)(-2 * as * (n + 2)) * (1.0f / 479.0f), &s2, &c2);
        float w0 = 479.0f * (1.0f - f), w1 = 479.0f * f;
        float2 t = make_float2(fmaf(w0, c1, w1 * c2), fmaf(w0, s1, w1 * s2));
        Ts[q][r] = t;
        Tt[r][q] = t;
        patch[q][r] = pv;
    }
    __syncthreads();

    int nwork = nrows * PP;    // 561 or 528 — one iteration per thread, no tail

    // ---- Stage 1: V[i][b] = sum_a Ts[i][a] * patch[a][b]   (complex x real)
    if (tid < nwork) {
        int li = tid / PP;                 // local row
        int bb = tid - li * PP;
        int i  = rowbase + li;
        const float4* trow = reinterpret_cast<const float4*>(Ts[i]);
        float rx = 0.f, ry = 0.f, rx2 = 0.f, ry2 = 0.f;
#pragma unroll
        for (int h = 0; h < 16; h++) {
            float4 tv = trow[h];
            float p0 = patch[2 * h][bb];
            float p1 = patch[2 * h + 1][bb];
            rx  = fmaf(tv.x, p0, rx);
            ry  = fmaf(tv.y, p0, ry);
            rx2 = fmaf(tv.z, p1, rx2);
            ry2 = fmaf(tv.w, p1, ry2);
        }
        float2 tl = Ts[i][32];
        float  pl = patch[32][bb];
        V[li][bb] = make_float2(fmaf(tl.x, pl, rx + rx2),
                                fmaf(tl.y, pl, ry + ry2));
    }
    __syncthreads();

    // ---- Stage 2: out[i][j] = sum_b V[i][b] * Tt[b][j]   (complex x complex)
    if (tid < nwork) {
        int li = tid / PP;
        int j  = tid - li * PP;
        int i  = rowbase + li;
        const float4* vrow = reinterpret_cast<const float4*>(V[li]);
        float rxx = 0.f, ryy = 0.f, rxy = 0.f, ryx = 0.f;
#pragma unroll
        for (int h = 0; h < 16; h++) {
            float4 vv = vrow[h];
            float2 t0 = Tt[2 * h][j];
            float2 t1 = Tt[2 * h + 1][j];
            rxx = fmaf(vv.x, t0.x, rxx);
            ryy = fmaf(vv.y, t0.y, ryy);
            rxy = fmaf(vv.x, t0.y, rxy);
            ryx = fmaf(vv.y, t0.x, ryx);
            rxx = fmaf(vv.z, t1.x, rxx);
            ryy = fmaf(vv.w, t1.y, ryy);
            rxy = fmaf(vv.z, t1.y, rxy);
            ryx = fmaf(vv.w, t1.x, ryx);
        }
        float2 vl = V[li][32];
        float2 tl = Tt[32][j];
        rxx = fmaf(vl.x, tl.x, rxx);
        ryy = fmaf(vl.y, tl.y, ryy);
        rxy = fmaf(vl.x, tl.y, rxy);
        ryx = fmaf(vl.y, tl.x, ryx);
        o[(size_t)i * PP + j] = make_float2(rxx - ryy, rxy + ryx);
    }
}

extern "C" void kernel_launch(void* const* d_in, const int* in_sizes, int n_in,
                              void* d_out, int out_size) {
    const float* ref = (const float*)d_in[0];
    const float* mov = (const float*)d_in[1];
    const int* xp = (n_in > 2) ? (const int*)d_in[2] : nullptr;
    const int* yp = (n_in > 3) ? (const int*)d_in[3] : nullptr;
    float* out = (float*)d_out;
    int B = in_sizes[0] / (IMG * IMG);

    taper_kernel<<<4 * B, NT>>>(ref, mov, xp, yp, out, B);
}